// round 16
// baseline (speedup 1.0000x reference)
#include <cuda_runtime.h>
#include <cuda_fp16.h>
#include <math.h>
#include <stdint.h>

#define NN 100000
#define EE 1600000
#define NBLK_SCAN ((NN + 1023) / 1024)
#define NTILES ((NN + 127) / 128)

// ---------------- device scratch (no allocations allowed) ----------------
__device__ int g_deg[NN];
__device__ int g_rowptr[NN + 1];
__device__ int g_csr[EE];
__device__ int g_rank[EE];
__device__ int g_blksum[NBLK_SCAN];

// fp16 activations (single copy serves gathers AND GEMM A-operands)
__device__ __half g_xh[(size_t)NN * 128];
__device__ __half g_aggh[(size_t)NN * 128];
__device__ __half g_h1h[(size_t)NN * 128];
__device__ __half g_t3h[(size_t)NN * 64];
__device__ float  g_r3[(size_t)NN * 64];
// fp16 weights (packed half2 words), w3c = combined [W3l;W3r]
__device__ unsigned g_w1l[8192], g_w1r[8192], g_w2l[8192], g_w2r[8192], g_w3c[8192];

// ---------------- merged: edge histogram + rank recording + fp16 prep ----------------
__global__ void k_histprep(const int* __restrict__ dst, int E,
                           const float* __restrict__ x,
                           const float* __restrict__ W1l, const float* __restrict__ W1r,
                           const float* __restrict__ W2l, const float* __restrict__ W2r,
                           const float* __restrict__ W3l, const float* __restrict__ W3r) {
    int i = blockIdx.x * blockDim.x + threadIdx.x;
    int e4 = E >> 2;
    if (i < e4) {                                  // histogram + rank, 4 edges/thread
        int4 d = ((const int4*)dst)[i];
        int4 r;
        r.x = atomicAdd(&g_deg[d.x], 1);
        r.y = atomicAdd(&g_deg[d.y], 1);
        r.z = atomicAdd(&g_deg[d.z], 1);
        r.w = atomicAdd(&g_deg[d.w], 1);
        ((int4*)g_rank)[i] = r;
        return;
    }
    int j = i - e4;
    if (j < NN * 32) {                             // x -> fp16, one float4 each
        float4 v = ((const float4*)x)[j];
        __half2* o = (__half2*)g_xh + 2 * j;
        o[0] = __float22half2_rn(make_float2(v.x, v.y));
        o[1] = __float22half2_rn(make_float2(v.z, v.w));
        return;
    }
    int id = j - NN * 32;                          // weights: 5 * 8192 half2 words
    if (id >= 5 * 8192) return;
    int tile = id >> 13, rem = id & 8191;
    int row = rem >> 6, wp = rem & 63;
    const float* srcs[4] = {W1l, W1r, W2l, W2r};
    const float* p;
    if (tile < 4) p = srcs[tile] + (size_t)row * 128 + wp * 2;
    else p = (row < 64) ? (W3l + (size_t)row * 128 + wp * 2)
                        : (W3r + (size_t)(row - 64) * 128 + wp * 2);
    float2 v = *(const float2*)p;
    __half2 h = __float22half2_rn(v);
    unsigned* dsts[5] = {g_w1l, g_w1r, g_w2l, g_w2r, g_w3c};
    dsts[tile][rem] = *(unsigned*)&h;
}

// warp-shuffle block scan (inclusive), 1024 threads
__global__ void k_scan1() {
    __shared__ int ws[32];
    int i = threadIdx.x;
    int gid = blockIdx.x * 1024 + i;
    int v = (gid < NN) ? g_deg[gid] : 0;
    int lane = i & 31, w = i >> 5;
    int xv = v;
#pragma unroll
    for (int o = 1; o < 32; o <<= 1) {
        int y = __shfl_up_sync(0xffffffffu, xv, o);
        if (lane >= o) xv += y;
    }
    if (lane == 31) ws[w] = xv;
    __syncthreads();
    if (w == 0) {
        int s = ws[lane];
#pragma unroll
        for (int o = 1; o < 32; o <<= 1) {
            int y = __shfl_up_sync(0xffffffffu, s, o);
            if (lane >= o) s += y;
        }
        ws[lane] = s;
    }
    __syncthreads();
    int incl = xv + ((w > 0) ? ws[w - 1] : 0);
    if (gid < NN) g_rowptr[gid] = incl - v;
    if (i == 1023) g_blksum[blockIdx.x] = incl;
}

// scan3: redundant per-block scan of the (<=128) block sums, then finalize rowptr
__global__ void k_scan3(int E) {
    __shared__ int s[128];
    int t = threadIdx.x;
    if (t < 128) {
        int v = (t < NBLK_SCAN) ? g_blksum[t] : 0;
        s[t] = v;
    }
    __syncthreads();
    if (t < 128) {
        for (int off = 1; off < 128; off <<= 1) {
            int a = (t >= off) ? s[t - off] : 0;
            __syncthreads();
            s[t] += a;
            __syncthreads();
        }
    } else {
        for (int off = 1; off < 128; off <<= 1) { __syncthreads(); __syncthreads(); }
    }
    int gid = blockIdx.x * blockDim.x + t;
    if (gid < NN) {
        int blk = gid >> 10;
        int pre = s[blk] - g_blksum[blk];   // exclusive prefix
        g_rowptr[gid] = g_rowptr[gid] + pre;
        g_deg[gid] = 0;   // pre-zero for the NEXT call (module-load state is also 0)
    } else if (gid == NN) {
        g_rowptr[NN] = E;
    }
}

// atomic-free scatter: pos = rowptr[dst] + rank (recorded during histogram)
__global__ void k_scatter(const int* __restrict__ src, const int* __restrict__ dst, int E) {
    int i = blockIdx.x * blockDim.x + threadIdx.x;
    if (i >= (E >> 2)) return;
    int4 d  = ((const int4*)dst)[i];
    int4 sv = ((const int4*)src)[i];
    int4 rk = ((const int4*)g_rank)[i];
    g_csr[g_rowptr[d.x] + rk.x] = sv.x;
    g_csr[g_rowptr[d.y] + rk.y] = sv.y;
    g_csr[g_rowptr[d.z] + rk.z] = sv.z;
    g_csr[g_rowptr[d.w] + rk.w] = sv.w;
}

// ---------------- mean aggregation (128-wide, half-warp per edge) ----------------
// fp16 pairwise reduction of 4 gathered rows + single fp32 accumulate,
// vectorized int4 index loads (issue-count minimization; kernel is issue-bound)
__device__ __forceinline__ uint4 hadd4(uint4 a, uint4 b) {
    __half2 r0 = __hadd2(*(__half2*)&a.x, *(__half2*)&b.x);
    __half2 r1 = __hadd2(*(__half2*)&a.y, *(__half2*)&b.y);
    __half2 r2 = __hadd2(*(__half2*)&a.z, *(__half2*)&b.z);
    __half2 r3 = __hadd2(*(__half2*)&a.w, *(__half2*)&b.w);
    return make_uint4(*(unsigned*)&r0, *(unsigned*)&r1,
                      *(unsigned*)&r2, *(unsigned*)&r3);
}

__device__ __forceinline__ void addu4(uint4 u, float* acc) {
    float2 f0 = __half22float2(*(__half2*)&u.x);
    float2 f1 = __half22float2(*(__half2*)&u.y);
    float2 f2 = __half22float2(*(__half2*)&u.z);
    float2 f3 = __half22float2(*(__half2*)&u.w);
    acc[0] += f0.x; acc[1] += f0.y; acc[2] += f1.x; acc[3] += f1.y;
    acc[4] += f2.x; acc[5] += f2.y; acc[6] += f3.x; acc[7] += f3.y;
}

__global__ void k_aggr128h(const __half* __restrict__ xh, __half* __restrict__ outh) {
    int wid = blockIdx.x * (blockDim.x >> 5) + (threadIdx.x >> 5);
    int lane = threadIdx.x & 31;
    if (wid >= NN) return;
    int beg = g_rowptr[wid], end = g_rowptr[wid + 1];
    int half = lane >> 4, sub = lane & 15;
    const uint4* base = (const uint4*)xh;    // 16 uint4 per 128-fp16 row
    float acc[8] = {0.f, 0.f, 0.f, 0.f, 0.f, 0.f, 0.f, 0.f};
    int j = beg;
    // prologue: align j to a 4-edge boundary (half 0 accumulates in fp32)
    while (j < end && (j & 3)) {
        if (half == 0) addu4(base[(size_t)g_csr[j] * 16 + sub], acc);
        j++;
    }
    // main: 8 edges/iter; one int4 index load per lane, fp16 tree, 1 fp32 add
    for (; j + 7 < end; j += 8) {
        int4 e = ((const int4*)(g_csr + j))[half];
        uint4 u0 = base[(size_t)(unsigned)e.x * 16 + sub];
        uint4 u1 = base[(size_t)(unsigned)e.y * 16 + sub];
        uint4 u2 = base[(size_t)(unsigned)e.z * 16 + sub];
        uint4 u3 = base[(size_t)(unsigned)e.w * 16 + sub];
        uint4 s = hadd4(hadd4(u0, u1), hadd4(u2, u3));
        addu4(s, acc);
    }
    // epilogue (<8 edges left)
    for (; j + 1 < end; j += 2) {
        uint4 u = base[(size_t)g_csr[j + half] * 16 + sub];
        addu4(u, acc);
    }
    if (j < end && half == 0) {
        uint4 u = base[(size_t)g_csr[j] * 16 + sub];
        addu4(u, acc);
    }
#pragma unroll
    for (int i = 0; i < 8; i++)
        acc[i] += __shfl_xor_sync(0xffffffffu, acc[i], 16);
    if (half == 0) {
        float inv = 1.f / fmaxf((float)(end - beg), 1.f);
        __half2 h0 = __float22half2_rn(make_float2(acc[0] * inv, acc[1] * inv));
        __half2 h1 = __float22half2_rn(make_float2(acc[2] * inv, acc[3] * inv));
        __half2 h2 = __float22half2_rn(make_float2(acc[4] * inv, acc[5] * inv));
        __half2 h3 = __float22half2_rn(make_float2(acc[6] * inv, acc[7] * inv));
        uint4 o = make_uint4(*(unsigned*)&h0, *(unsigned*)&h1,
                             *(unsigned*)&h2, *(unsigned*)&h3);
        ((uint4*)outh)[(size_t)wid * 16 + sub] = o;
    }
}

// ---------------- fused agg64 + add + log_softmax (warp per node) ----------------
__global__ void k_agg_lsm(const __half* __restrict__ t3h, const float* __restrict__ r3,
                          float* __restrict__ out) {
    int wid = blockIdx.x * (blockDim.x >> 5) + (threadIdx.x >> 5);
    int lane = threadIdx.x & 31;
    if (wid >= NN) return;
    int beg = g_rowptr[wid], end = g_rowptr[wid + 1];
    const unsigned* base = (const unsigned*)t3h;   // 32 half2 words per 64-fp16 row
    float a0 = 0.f, a1 = 0.f;
    int j = beg;
    for (; j + 3 < end; j += 4) {
        int s0 = g_csr[j], s1 = g_csr[j + 1], s2 = g_csr[j + 2], s3 = g_csr[j + 3];
        unsigned u0 = base[(size_t)s0 * 32 + lane];
        unsigned u1 = base[(size_t)s1 * 32 + lane];
        unsigned u2 = base[(size_t)s2 * 32 + lane];
        unsigned u3 = base[(size_t)s3 * 32 + lane];
        float2 f0 = __half22float2(*(__half2*)&u0);
        float2 f1 = __half22float2(*(__half2*)&u1);
        float2 f2 = __half22float2(*(__half2*)&u2);
        float2 f3 = __half22float2(*(__half2*)&u3);
        a0 += (f0.x + f1.x) + (f2.x + f3.x);
        a1 += (f0.y + f1.y) + (f2.y + f3.y);
    }
    for (; j < end; j++) {
        unsigned u0 = base[(size_t)g_csr[j] * 32 + lane];
        float2 f0 = __half22float2(*(__half2*)&u0);
        a0 += f0.x; a1 += f0.y;
    }
    float inv = 1.f / fmaxf((float)(end - beg), 1.f);
    float2 rv = *(const float2*)(r3 + (size_t)wid * 64 + lane * 2);
    float v0 = rv.x + a0 * inv;
    float v1 = rv.y + a1 * inv;
    float m = fmaxf(v0, v1);
#pragma unroll
    for (int o = 16; o > 0; o >>= 1) m = fmaxf(m, __shfl_xor_sync(0xffffffffu, m, o));
    float s = expf(v0 - m) + expf(v1 - m);
#pragma unroll
    for (int o = 16; o > 0; o >>= 1) s += __shfl_xor_sync(0xffffffffu, s, o);
    float l = m + logf(s);
    *(float2*)(out + (size_t)wid * 64 + lane * 2) = make_float2(v0 - l, v1 - l);
}

// ---------------- GEMM machinery: cp.async pipeline + fp16 MMA ----------------
#define MMA_F16(C, A, b0, b1)                                                 \
    asm volatile(                                                             \
        "mma.sync.aligned.m16n8k16.row.col.f32.f16.f16.f32 "                  \
        "{%0,%1,%2,%3},{%4,%5,%6,%7},{%8,%9},{%0,%1,%2,%3};"                  \
        : "+f"((C)[0]), "+f"((C)[1]), "+f"((C)[2]), "+f"((C)[3])              \
        : "r"((A)[0]), "r"((A)[1]), "r"((A)[2]), "r"((A)[3]),                 \
          "r"(b0), "r"(b1))

__device__ __forceinline__ uint32_t su32(const void* p) {
    uint32_t a;
    asm("{ .reg .u64 t; cvta.to.shared.u64 t, %1; cvt.u32.u64 %0, t; }" : "=r"(a) : "l"(p));
    return a;
}

#define SWZB(o) ((o) ^ (((o) >> 3) & 0x30))
#define STAGE_B 16384     // A+W: 2 x 128 rows x 64B (32 fp16 K-chunk)
#define STAGES 3
#define DSMEM  (STAGES * STAGE_B + 128)
#define DSMEM3 (4 * STAGE_B + 128)

__device__ __forceinline__ void issue_chunk(uint32_t sbase,
    const unsigned* __restrict__ A, const unsigned* __restrict__ W,
    int k0w, int row0, int t)
{
#pragma unroll
    for (int tn = 0; tn < 2; tn++) {
#pragma unroll
        for (int j = 0; j < 2; j++) {
            int idx = t + j * 256;
            int row = idx >> 2, c16 = idx & 3;
            uint32_t dstp = sbase + tn * 8192 + SWZB(row * 64 + c16 * 16);
            const unsigned* bp;
            int sz = 16;
            if (tn == 0) {
                int gr = row0 + row;
                if (gr >= NN) { sz = 0; gr = NN - 1; }
                bp = A + (size_t)gr * 64 + k0w + c16 * 4;
            } else {
                bp = W + (size_t)row * 64 + k0w + c16 * 4;
            }
            asm volatile("cp.async.cg.shared.global [%0], [%1], 16, %2;"
                         :: "r"(dstp), "l"(bp), "r"(sz) : "memory");
        }
    }
    asm volatile("cp.async.commit_group;" ::: "memory");
}

__device__ __forceinline__ void mma_chunk(const char* Am, const char* Wm,
                                          float c[2][8][4], int wr, int wc,
                                          int g, int tg)
{
#pragma unroll
    for (int ks = 0; ks < 2; ks++) {
        const int kw = ks * 8;
        unsigned a[2][4];
#pragma unroll
        for (int mt = 0; mt < 2; mt++) {
            int r = wr * 32 + mt * 16 + g;
            a[mt][0] = *(const unsigned*)(Am + SWZB(r * 64 + (kw + tg) * 4));
            a[mt][1] = *(const unsigned*)(Am + SWZB((r + 8) * 64 + (kw + tg) * 4));
            a[mt][2] = *(const unsigned*)(Am + SWZB(r * 64 + (kw + tg + 4) * 4));
            a[mt][3] = *(const unsigned*)(Am + SWZB((r + 8) * 64 + (kw + tg + 4) * 4));
        }
#pragma unroll
        for (int nt = 0; nt < 8; nt++) {
            int n = wc * 64 + nt * 8 + g;
            unsigned b0 = *(const unsigned*)(Wm + SWZB(n * 64 + (kw + tg) * 4));
            unsigned b1 = *(const unsigned*)(Wm + SWZB(n * 64 + (kw + tg + 4) * 4));
#pragma unroll
            for (int mt = 0; mt < 2; mt++)
                MMA_F16(c[mt][nt], a[mt], b0, b1);
        }
    }
}

// ---------------- layer-1 dual GEMM + BN + ReLU -> fp16 ----------------
__global__ __launch_bounds__(256, 2) void k_gemm_dual(
    const unsigned* __restrict__ A0, const unsigned* __restrict__ W0,
    const unsigned* __restrict__ A1, const unsigned* __restrict__ W1,
    const float* __restrict__ bias, const float* __restrict__ gamma,
    const float* __restrict__ beta, const float* __restrict__ rmean,
    const float* __restrict__ rvar, __half* __restrict__ outh)
{
    extern __shared__ uint4 dyn4[];
    __shared__ float s_sc[128], s_sh[128];
    const int t = threadIdx.x;
    const int lane = t & 31, wid = t >> 5;
    const int wr = wid & 3, wc = wid >> 2;
    const int g = lane >> 2, tg = lane & 3;
    const int row0 = blockIdx.x * 128;

    uint32_t sb0 = su32(dyn4);
    uint32_t ab = (sb0 + 127u) & ~127u;
    const char* smbase = (const char*)dyn4 + (ab - sb0);

    if (t < 128) {
        float s = gamma[t] * rsqrtf(rvar[t] + 1e-5f);
        s_sc[t] = s;
        s_sh[t] = beta[t] + (bias[t] - rmean[t]) * s;
    }

    float c[2][8][4];
#pragma unroll
    for (int mt = 0; mt < 2; mt++)
#pragma unroll
        for (int nt = 0; nt < 8; nt++)
#pragma unroll
            for (int q = 0; q < 4; q++) c[mt][nt][q] = 0.f;

#pragma unroll
    for (int s = 0; s < STAGES; s++)
        issue_chunk(ab + s * STAGE_B, A0, W0, s * 16, row0, t);

#pragma unroll
    for (int cc = 0; cc < 8; cc++) {
        asm volatile("cp.async.wait_group 2;" ::: "memory");
        __syncthreads();
        const char* sm = smbase + (cc % 3) * STAGE_B;
        mma_chunk(sm, sm + 8192, c, wr, wc, g, tg);
        __syncthreads();
        if (cc + STAGES < 8) {
            int nc = cc + STAGES;
            int pass = nc >> 2;
            issue_chunk(ab + (nc % 3) * STAGE_B,
                        pass ? A1 : A0, pass ? W1 : W0, (nc & 3) * 16, row0, t);
        } else {
            asm volatile("cp.async.commit_group;" ::: "memory");
        }
    }

#pragma unroll
    for (int mt = 0; mt < 2; mt++) {
#pragma unroll
        for (int i = 0; i < 2; i++) {
            int r = row0 + wr * 32 + mt * 16 + g + i * 8;
            if (r >= NN) continue;
#pragma unroll
            for (int nt = 0; nt < 8; nt++) {
                int col = wc * 64 + nt * 8 + 2 * tg;
                float v0 = c[mt][nt][2 * i];
                float v1 = c[mt][nt][2 * i + 1];
                v0 = fmaxf(v0 * s_sc[col] + s_sh[col], 0.f);
                v1 = fmaxf(v1 * s_sc[col + 1] + s_sh[col + 1], 0.f);
                *(__half2*)(outh + (size_t)r * 128 + col) =
                    __float22half2_rn(make_float2(v0, v1));
            }
        }
    }
}

// ---------------- layer-2 dual GEMM + BN + ReLU fused with layer-3 GEMM ----------------
__global__ __launch_bounds__(256, 2) void k_gemm_dual_l2(
    const unsigned* __restrict__ A0, const unsigned* __restrict__ W0,
    const unsigned* __restrict__ A1, const unsigned* __restrict__ W1,
    const float* __restrict__ bias, const float* __restrict__ gamma,
    const float* __restrict__ beta, const float* __restrict__ rmean,
    const float* __restrict__ rvar,
    const unsigned* __restrict__ W3, const float* __restrict__ b3,
    __half* __restrict__ t3h, float* __restrict__ r3)
{
    extern __shared__ uint4 dyn4[];
    __shared__ float s_sc[128], s_sh[128];
    const int t = threadIdx.x;
    const int lane = t & 31, wid = t >> 5;
    const int wr = wid & 3, wc = wid >> 2;
    const int g = lane >> 2, tg = lane & 3;
    const int row0 = blockIdx.x * 128;

    uint32_t sb0 = su32(dyn4);
    uint32_t ab = (sb0 + 127u) & ~127u;
    char* smbase = (char*)dyn4 + (ab - sb0);

    if (t < 128) {
        float s = gamma[t] * rsqrtf(rvar[t] + 1e-5f);
        s_sc[t] = s;
        s_sh[t] = beta[t] + (bias[t] - rmean[t]) * s;
    }

    float c[2][8][4];
#pragma unroll
    for (int mt = 0; mt < 2; mt++)
#pragma unroll
        for (int nt = 0; nt < 8; nt++)
#pragma unroll
            for (int q = 0; q < 4; q++) c[mt][nt][q] = 0.f;

#pragma unroll
    for (int s = 0; s < STAGES; s++)
        issue_chunk(ab + s * STAGE_B, A0, W0, s * 16, row0, t);

#pragma unroll
    for (int cc = 0; cc < 8; cc++) {
        asm volatile("cp.async.wait_group 2;" ::: "memory");
        __syncthreads();
        const char* sm = smbase + (cc % 3) * STAGE_B;
        mma_chunk(sm, sm + 8192, c, wr, wc, g, tg);
        __syncthreads();
        if (cc + STAGES < 8) {
            int nc = cc + STAGES;
            int pass = nc >> 2;
            issue_chunk(ab + (nc % 3) * STAGE_B,
                        pass ? A1 : A0, pass ? W1 : W0, (nc & 3) * 16, row0, t);
        } else {
            asm volatile("cp.async.commit_group;" ::: "memory");
        }
    }
    asm volatile("cp.async.wait_group 0;" ::: "memory");
    __syncthreads();

    // stage W3c (32KB) into smem upper half via cp.async
#pragma unroll
    for (int kc = 0; kc < 4; kc++) {
#pragma unroll
        for (int j = 0; j < 2; j++) {
            int idx = t + j * 256;
            int row = idx >> 2, c16 = idx & 3;
            uint32_t dstp = ab + 32768 + kc * 8192 + SWZB(row * 64 + c16 * 16);
            const unsigned* bp = W3 + (size_t)row * 64 + kc * 16 + c16 * 4;
            asm volatile("cp.async.cg.shared.global [%0], [%1], 16, 16;"
                         :: "r"(dstp), "l"(bp) : "memory");
        }
    }
    asm volatile("cp.async.commit_group;" ::: "memory");

    // BN + ReLU -> fp16 h2 tile into smem lower half
#pragma unroll
    for (int mt = 0; mt < 2; mt++) {
#pragma unroll
        for (int i = 0; i < 2; i++) {
            int rl = wr * 32 + mt * 16 + g + i * 8;
#pragma unroll
            for (int nt = 0; nt < 8; nt++) {
                int col = wc * 64 + nt * 8 + 2 * tg;
                float v0 = fmaxf(c[mt][nt][2 * i] * s_sc[col] + s_sh[col], 0.f);
                float v1 = fmaxf(c[mt][nt][2 * i + 1] * s_sc[col + 1] + s_sh[col + 1], 0.f);
                __half2 h = __float22half2_rn(make_float2(v0, v1));
                int kc = col >> 5;
                int off = kc * 8192 + SWZB(rl * 64 + ((col & 31) >> 1) * 4);
                *(unsigned*)(smbase + off) = *(unsigned*)&h;
            }
        }
    }
    asm volatile("cp.async.wait_group 0;" ::: "memory");
    __syncthreads();

    // layer-3 GEMM: h2_tile @ W3c
#pragma unroll
    for (int mt = 0; mt < 2; mt++)
#pragma unroll
        for (int nt = 0; nt < 8; nt++)
#pragma unroll
            for (int q = 0; q < 4; q++) c[mt][nt][q] = 0.f;

#pragma unroll
    for (int kc = 0; kc < 4; kc++)
        mma_chunk(smbase + kc * 8192, smbase + 32768 + kc * 8192, c, wr, wc, g, tg);

#pragma unroll
    for (int mt = 0; mt < 2; mt++) {
#pragma unroll
        for (int i = 0; i < 2; i++) {
            int r = row0 + wr * 32 + mt * 16 + g + i * 8;
            if (r >= NN) continue;
#pragma unroll
            for (int nt = 0; nt < 8; nt++) {
                int col = wc * 64 + nt * 8 + 2 * tg;
                float v0 = c[mt][nt][2 * i];
                float v1 = c[mt][nt][2 * i + 1];
                if (col < 64) {
                    *(__half2*)(t3h + (size_t)r * 64 + col) =
                        __float22half2_rn(make_float2(v0, v1));
                } else {
                    int cc2 = col - 64;
                    v0 += b3[cc2]; v1 += b3[cc2 + 1];
                    *(float2*)(r3 + (size_t)r * 64 + cc2) = make_float2(v0, v1);
                }
            }
        }
    }
}

// ---------------- launch ----------------
extern "C" void kernel_launch(void* const* d_in, const int* in_sizes, int n_in,
                              void* d_out, int out_size) {
    const float* x   = (const float*)d_in[0];
    const int*   src = (const int*)d_in[1];
    const int*   dst = (const int*)d_in[2];
    const float* W1l = (const float*)d_in[3];
    const float* W1r = (const float*)d_in[4];
    const float* b1  = (const float*)d_in[5];
    const float* g1  = (const float*)d_in[6];
    const float* be1 = (const float*)d_in[7];
    const float* rm1 = (const float*)d_in[8];
    const float* rv1 = (const float*)d_in[9];
    const float* W2l = (const float*)d_in[10];
    const float* W2r = (const float*)d_in[11];
    const float* b2  = (const float*)d_in[12];
    const float* g2  = (const float*)d_in[13];
    const float* be2 = (const float*)d_in[14];
    const float* rm2 = (const float*)d_in[15];
    const float* rv2 = (const float*)d_in[16];
    const float* W3l = (const float*)d_in[17];
    const float* W3r = (const float*)d_in[18];
    const float* b3  = (const float*)d_in[19];
    float* out = (float*)d_out;
    int E = in_sizes[1];

    __half *p_xh, *p_aggh, *p_h1h, *p_t3h;
    float *p_r3;
    unsigned *p_w1l, *p_w1r, *p_w2l, *p_w2r, *p_w3c;
    cudaGetSymbolAddress((void**)&p_xh,   g_xh);
    cudaGetSymbolAddress((void**)&p_aggh, g_aggh);
    cudaGetSymbolAddress((void**)&p_h1h,  g_h1h);
    cudaGetSymbolAddress((void**)&p_t3h,  g_t3h);
    cudaGetSymbolAddress((void**)&p_r3,   g_r3);
    cudaGetSymbolAddress((void**)&p_w1l,  g_w1l);
    cudaGetSymbolAddress((void**)&p_w1r,  g_w1r);
    cudaGetSymbolAddress((void**)&p_w2l,  g_w2l);
    cudaGetSymbolAddress((void**)&p_w2r,  g_w2r);
    cudaGetSymbolAddress((void**)&p_w3c,  g_w3c);

    cudaFuncSetAttribute(k_gemm_dual,
                         cudaFuncAttributeMaxDynamicSharedMemorySize, DSMEM);
    cudaFuncSetAttribute(k_gemm_dual_l2,
                         cudaFuncAttributeMaxDynamicSharedMemorySize, DSMEM3);

    // merged histogram (+rank) + fp16 prep
    int total = (E >> 2) + NN * 32 + 5 * 8192;
    k_histprep<<<(total + 255) / 256, 256>>>(dst, E, x, W1l, W1r, W2l, W2r, W3l, W3r);
    k_scan1<<<NBLK_SCAN, 1024>>>();
    k_scan3<<<(NN + 1 + 255) / 256, 256>>>(E);
    k_scatter<<<((E >> 2) + 255) / 256, 256>>>(src, dst, E);

    const int gemm_blocks = NTILES;

    // layer 1
    k_aggr128h<<<NN / 8, 256>>>(p_xh, p_aggh);
    k_gemm_dual<<<gemm_blocks, 256, DSMEM>>>(
        (const unsigned*)p_aggh, p_w1l, (const unsigned*)p_xh, p_w1r,
        b1, g1, be1, rm1, rv1, p_h1h);
    // layer 2 + layer-3 GEMM fused
    k_aggr128h<<<NN / 8, 256>>>(p_h1h, p_aggh);
    k_gemm_dual_l2<<<gemm_blocks, 256, DSMEM3>>>(
        (const unsigned*)p_aggh, p_w2l, (const unsigned*)p_h1h, p_w2r,
        b2, g2, be2, rm2, rv2, p_w3c, b3, p_t3h, p_r3);
    // layer 3 aggregation + log_softmax fused
    k_agg_lsm<<<NN / 8, 256>>>(p_t3h, p_r3, out);
}

// round 17
// speedup vs baseline: 1.1525x; 1.1525x over previous
#include <cuda_runtime.h>
#include <cuda_fp16.h>
#include <math.h>
#include <stdint.h>

#define NN 100000
#define EE 1600000
#define NBLK_SCAN ((NN + 1023) / 1024)
#define NTILES ((NN + 127) / 128)

// ---------------- device scratch (no allocations allowed) ----------------
__device__ int g_deg[NN];
__device__ int g_rowptr[NN + 1];
__device__ int g_csr[EE];
__device__ int g_rank[EE];
__device__ int g_blksum[NBLK_SCAN];

// fp16 activations (single copy serves gathers AND GEMM A-operands)
__device__ __half g_xh[(size_t)NN * 128];
__device__ __half g_aggh[(size_t)NN * 128];
__device__ __half g_h1h[(size_t)NN * 128];
__device__ __half g_t3h[(size_t)NN * 64];
__device__ float  g_r3[(size_t)NN * 64];
// fp16 weights (packed half2 words), w3c = combined [W3l;W3r]
__device__ unsigned g_w1l[8192], g_w1r[8192], g_w2l[8192], g_w2r[8192], g_w3c[8192];

// ---------------- merged: edge histogram + rank recording + fp16 prep ----------------
__global__ void k_histprep(const int* __restrict__ dst, int E,
                           const float* __restrict__ x,
                           const float* __restrict__ W1l, const float* __restrict__ W1r,
                           const float* __restrict__ W2l, const float* __restrict__ W2r,
                           const float* __restrict__ W3l, const float* __restrict__ W3r) {
    int i = blockIdx.x * blockDim.x + threadIdx.x;
    int e4 = E >> 2;
    if (i < e4) {                                  // histogram + rank, 4 edges/thread
        int4 d = ((const int4*)dst)[i];
        int4 r;
        r.x = atomicAdd(&g_deg[d.x], 1);
        r.y = atomicAdd(&g_deg[d.y], 1);
        r.z = atomicAdd(&g_deg[d.z], 1);
        r.w = atomicAdd(&g_deg[d.w], 1);
        ((int4*)g_rank)[i] = r;
        return;
    }
    int j = i - e4;
    if (j < NN * 32) {                             // x -> fp16, one float4 each
        float4 v = ((const float4*)x)[j];
        __half2* o = (__half2*)g_xh + 2 * j;
        o[0] = __float22half2_rn(make_float2(v.x, v.y));
        o[1] = __float22half2_rn(make_float2(v.z, v.w));
        return;
    }
    int id = j - NN * 32;                          // weights: 5 * 8192 half2 words
    if (id >= 5 * 8192) return;
    int tile = id >> 13, rem = id & 8191;
    int row = rem >> 6, wp = rem & 63;
    const float* srcs[4] = {W1l, W1r, W2l, W2r};
    const float* p;
    if (tile < 4) p = srcs[tile] + (size_t)row * 128 + wp * 2;
    else p = (row < 64) ? (W3l + (size_t)row * 128 + wp * 2)
                        : (W3r + (size_t)(row - 64) * 128 + wp * 2);
    float2 v = *(const float2*)p;
    __half2 h = __float22half2_rn(v);
    unsigned* dsts[5] = {g_w1l, g_w1r, g_w2l, g_w2r, g_w3c};
    dsts[tile][rem] = *(unsigned*)&h;
}

// warp-shuffle block scan (inclusive), 1024 threads
__global__ void k_scan1() {
    __shared__ int ws[32];
    int i = threadIdx.x;
    int gid = blockIdx.x * 1024 + i;
    int v = (gid < NN) ? g_deg[gid] : 0;
    int lane = i & 31, w = i >> 5;
    int xv = v;
#pragma unroll
    for (int o = 1; o < 32; o <<= 1) {
        int y = __shfl_up_sync(0xffffffffu, xv, o);
        if (lane >= o) xv += y;
    }
    if (lane == 31) ws[w] = xv;
    __syncthreads();
    if (w == 0) {
        int s = ws[lane];
#pragma unroll
        for (int o = 1; o < 32; o <<= 1) {
            int y = __shfl_up_sync(0xffffffffu, s, o);
            if (lane >= o) s += y;
        }
        ws[lane] = s;
    }
    __syncthreads();
    int incl = xv + ((w > 0) ? ws[w - 1] : 0);
    if (gid < NN) g_rowptr[gid] = incl - v;
    if (i == 1023) g_blksum[blockIdx.x] = incl;
}

// scan3: redundant per-block scan of the (<=128) block sums, then finalize rowptr
__global__ void k_scan3(int E) {
    __shared__ int s[128];
    int t = threadIdx.x;
    if (t < 128) {
        int v = (t < NBLK_SCAN) ? g_blksum[t] : 0;
        s[t] = v;
    }
    __syncthreads();
    if (t < 128) {
        for (int off = 1; off < 128; off <<= 1) {
            int a = (t >= off) ? s[t - off] : 0;
            __syncthreads();
            s[t] += a;
            __syncthreads();
        }
    } else {
        for (int off = 1; off < 128; off <<= 1) { __syncthreads(); __syncthreads(); }
    }
    int gid = blockIdx.x * blockDim.x + t;
    if (gid < NN) {
        int blk = gid >> 10;
        int pre = s[blk] - g_blksum[blk];   // exclusive prefix
        g_rowptr[gid] = g_rowptr[gid] + pre;
        g_deg[gid] = 0;   // pre-zero for the NEXT call (module-load state is also 0)
    } else if (gid == NN) {
        g_rowptr[NN] = E;
    }
}

// atomic-free scatter: pos = rowptr[dst] + rank (recorded during histogram)
__global__ void k_scatter(const int* __restrict__ src, const int* __restrict__ dst, int E) {
    int i = blockIdx.x * blockDim.x + threadIdx.x;
    if (i >= (E >> 2)) return;
    int4 d  = ((const int4*)dst)[i];
    int4 sv = ((const int4*)src)[i];
    int4 rk = ((const int4*)g_rank)[i];
    g_csr[g_rowptr[d.x] + rk.x] = sv.x;
    g_csr[g_rowptr[d.y] + rk.y] = sv.y;
    g_csr[g_rowptr[d.z] + rk.z] = sv.z;
    g_csr[g_rowptr[d.w] + rk.w] = sv.w;
}

// ---------------- mean aggregation (128-wide, half-warp per edge) ----------------
__device__ __forceinline__ void addu4(uint4 u, float* acc) {
    float2 f0 = __half22float2(*(__half2*)&u.x);
    float2 f1 = __half22float2(*(__half2*)&u.y);
    float2 f2 = __half22float2(*(__half2*)&u.z);
    float2 f3 = __half22float2(*(__half2*)&u.w);
    acc[0] += f0.x; acc[1] += f0.y; acc[2] += f1.x; acc[3] += f1.y;
    acc[4] += f2.x; acc[5] += f2.y; acc[6] += f3.x; acc[7] += f3.y;
}

__global__ void k_aggr128h(const __half* __restrict__ xh, __half* __restrict__ outh) {
    int wid = blockIdx.x * (blockDim.x >> 5) + (threadIdx.x >> 5);
    int lane = threadIdx.x & 31;
    if (wid >= NN) return;
    int beg = g_rowptr[wid], end = g_rowptr[wid + 1];
    int half = lane >> 4, sub = lane & 15;
    const uint4* base = (const uint4*)xh;    // 16 uint4 per 128-fp16 row
    float acc[8] = {0.f, 0.f, 0.f, 0.f, 0.f, 0.f, 0.f, 0.f};
    int j = beg;
    for (; j + 7 < end; j += 8) {
        int e0 = g_csr[j + half * 4 + 0];
        int e1 = g_csr[j + half * 4 + 1];
        int e2 = g_csr[j + half * 4 + 2];
        int e3 = g_csr[j + half * 4 + 3];
        uint4 u0 = base[(size_t)e0 * 16 + sub];
        uint4 u1 = base[(size_t)e1 * 16 + sub];
        uint4 u2 = base[(size_t)e2 * 16 + sub];
        uint4 u3 = base[(size_t)e3 * 16 + sub];
        addu4(u0, acc); addu4(u1, acc); addu4(u2, acc); addu4(u3, acc);
    }
    for (; j + 1 < end; j += 2) {
        int e = g_csr[j + half];
        uint4 u = base[(size_t)e * 16 + sub];
        addu4(u, acc);
    }
    if (j < end && half == 0) {
        uint4 u = base[(size_t)g_csr[j] * 16 + sub];
        addu4(u, acc);
    }
#pragma unroll
    for (int i = 0; i < 8; i++)
        acc[i] += __shfl_xor_sync(0xffffffffu, acc[i], 16);
    if (half == 0) {
        float inv = 1.f / fmaxf((float)(end - beg), 1.f);
        __half2 h0 = __float22half2_rn(make_float2(acc[0] * inv, acc[1] * inv));
        __half2 h1 = __float22half2_rn(make_float2(acc[2] * inv, acc[3] * inv));
        __half2 h2 = __float22half2_rn(make_float2(acc[4] * inv, acc[5] * inv));
        __half2 h3 = __float22half2_rn(make_float2(acc[6] * inv, acc[7] * inv));
        uint4 o = make_uint4(*(unsigned*)&h0, *(unsigned*)&h1,
                             *(unsigned*)&h2, *(unsigned*)&h3);
        ((uint4*)outh)[(size_t)wid * 16 + sub] = o;
    }
}

// ---------------- fused agg64 + add + log_softmax (warp per node) ----------------
__global__ void k_agg_lsm(const __half* __restrict__ t3h, const float* __restrict__ r3,
                          float* __restrict__ out) {
    int wid = blockIdx.x * (blockDim.x >> 5) + (threadIdx.x >> 5);
    int lane = threadIdx.x & 31;
    if (wid >= NN) return;
    int beg = g_rowptr[wid], end = g_rowptr[wid + 1];
    const unsigned* base = (const unsigned*)t3h;   // 32 half2 words per 64-fp16 row
    float a0 = 0.f, a1 = 0.f;
    int j = beg;
    for (; j + 3 < end; j += 4) {
        int s0 = g_csr[j], s1 = g_csr[j + 1], s2 = g_csr[j + 2], s3 = g_csr[j + 3];
        unsigned u0 = base[(size_t)s0 * 32 + lane];
        unsigned u1 = base[(size_t)s1 * 32 + lane];
        unsigned u2 = base[(size_t)s2 * 32 + lane];
        unsigned u3 = base[(size_t)s3 * 32 + lane];
        float2 f0 = __half22float2(*(__half2*)&u0);
        float2 f1 = __half22float2(*(__half2*)&u1);
        float2 f2 = __half22float2(*(__half2*)&u2);
        float2 f3 = __half22float2(*(__half2*)&u3);
        a0 += (f0.x + f1.x) + (f2.x + f3.x);
        a1 += (f0.y + f1.y) + (f2.y + f3.y);
    }
    for (; j < end; j++) {
        unsigned u0 = base[(size_t)g_csr[j] * 32 + lane];
        float2 f0 = __half22float2(*(__half2*)&u0);
        a0 += f0.x; a1 += f0.y;
    }
    float inv = 1.f / fmaxf((float)(end - beg), 1.f);
    float2 rv = *(const float2*)(r3 + (size_t)wid * 64 + lane * 2);
    float v0 = rv.x + a0 * inv;
    float v1 = rv.y + a1 * inv;
    float m = fmaxf(v0, v1);
#pragma unroll
    for (int o = 16; o > 0; o >>= 1) m = fmaxf(m, __shfl_xor_sync(0xffffffffu, m, o));
    float s = expf(v0 - m) + expf(v1 - m);
#pragma unroll
    for (int o = 16; o > 0; o >>= 1) s += __shfl_xor_sync(0xffffffffu, s, o);
    float l = m + logf(s);
    *(float2*)(out + (size_t)wid * 64 + lane * 2) = make_float2(v0 - l, v1 - l);
}

// ---------------- GEMM machinery: cp.async pipeline + fp16 MMA ----------------
#define MMA_F16(C, A, b0, b1)                                                 \
    asm volatile(                                                             \
        "mma.sync.aligned.m16n8k16.row.col.f32.f16.f16.f32 "                  \
        "{%0,%1,%2,%3},{%4,%5,%6,%7},{%8,%9},{%0,%1,%2,%3};"                  \
        : "+f"((C)[0]), "+f"((C)[1]), "+f"((C)[2]), "+f"((C)[3])              \
        : "r"((A)[0]), "r"((A)[1]), "r"((A)[2]), "r"((A)[3]),                 \
          "r"(b0), "r"(b1))

__device__ __forceinline__ uint32_t su32(const void* p) {
    uint32_t a;
    asm("{ .reg .u64 t; cvta.to.shared.u64 t, %1; cvt.u32.u64 %0, t; }" : "=r"(a) : "l"(p));
    return a;
}

#define SWZB(o) ((o) ^ (((o) >> 3) & 0x30))
#define STAGE_B 16384     // A+W: 2 x 128 rows x 64B (32 fp16 K-chunk)
#define STAGES 3
#define DSMEM  (STAGES * STAGE_B + 128)
#define DSMEM3 (4 * STAGE_B + 128)

__device__ __forceinline__ void issue_chunk(uint32_t sbase,
    const unsigned* __restrict__ A, const unsigned* __restrict__ W,
    int k0w, int row0, int t)
{
#pragma unroll
    for (int tn = 0; tn < 2; tn++) {
#pragma unroll
        for (int j = 0; j < 2; j++) {
            int idx = t + j * 256;
            int row = idx >> 2, c16 = idx & 3;
            uint32_t dstp = sbase + tn * 8192 + SWZB(row * 64 + c16 * 16);
            const unsigned* bp;
            int sz = 16;
            if (tn == 0) {
                int gr = row0 + row;
                if (gr >= NN) { sz = 0; gr = NN - 1; }
                bp = A + (size_t)gr * 64 + k0w + c16 * 4;
            } else {
                bp = W + (size_t)row * 64 + k0w + c16 * 4;
            }
            asm volatile("cp.async.cg.shared.global [%0], [%1], 16, %2;"
                         :: "r"(dstp), "l"(bp), "r"(sz) : "memory");
        }
    }
    asm volatile("cp.async.commit_group;" ::: "memory");
}

__device__ __forceinline__ void mma_chunk(const char* Am, const char* Wm,
                                          float c[2][8][4], int wr, int wc,
                                          int g, int tg)
{
#pragma unroll
    for (int ks = 0; ks < 2; ks++) {
        const int kw = ks * 8;
        unsigned a[2][4];
#pragma unroll
        for (int mt = 0; mt < 2; mt++) {
            int r = wr * 32 + mt * 16 + g;
            a[mt][0] = *(const unsigned*)(Am + SWZB(r * 64 + (kw + tg) * 4));
            a[mt][1] = *(const unsigned*)(Am + SWZB((r + 8) * 64 + (kw + tg) * 4));
            a[mt][2] = *(const unsigned*)(Am + SWZB(r * 64 + (kw + tg + 4) * 4));
            a[mt][3] = *(const unsigned*)(Am + SWZB((r + 8) * 64 + (kw + tg + 4) * 4));
        }
#pragma unroll
        for (int nt = 0; nt < 8; nt++) {
            int n = wc * 64 + nt * 8 + g;
            unsigned b0 = *(const unsigned*)(Wm + SWZB(n * 64 + (kw + tg) * 4));
            unsigned b1 = *(const unsigned*)(Wm + SWZB(n * 64 + (kw + tg + 4) * 4));
#pragma unroll
            for (int mt = 0; mt < 2; mt++)
                MMA_F16(c[mt][nt], a[mt], b0, b1);
        }
    }
}

// ---------------- layer-1 dual GEMM + BN + ReLU -> fp16 ----------------
__global__ __launch_bounds__(256, 2) void k_gemm_dual(
    const unsigned* __restrict__ A0, const unsigned* __restrict__ W0,
    const unsigned* __restrict__ A1, const unsigned* __restrict__ W1,
    const float* __restrict__ bias, const float* __restrict__ gamma,
    const float* __restrict__ beta, const float* __restrict__ rmean,
    const float* __restrict__ rvar, __half* __restrict__ outh)
{
    extern __shared__ uint4 dyn4[];
    __shared__ float s_sc[128], s_sh[128];
    const int t = threadIdx.x;
    const int lane = t & 31, wid = t >> 5;
    const int wr = wid & 3, wc = wid >> 2;
    const int g = lane >> 2, tg = lane & 3;
    const int row0 = blockIdx.x * 128;

    uint32_t sb0 = su32(dyn4);
    uint32_t ab = (sb0 + 127u) & ~127u;
    const char* smbase = (const char*)dyn4 + (ab - sb0);

    if (t < 128) {
        float s = gamma[t] * rsqrtf(rvar[t] + 1e-5f);
        s_sc[t] = s;
        s_sh[t] = beta[t] + (bias[t] - rmean[t]) * s;
    }

    float c[2][8][4];
#pragma unroll
    for (int mt = 0; mt < 2; mt++)
#pragma unroll
        for (int nt = 0; nt < 8; nt++)
#pragma unroll
            for (int q = 0; q < 4; q++) c[mt][nt][q] = 0.f;

#pragma unroll
    for (int s = 0; s < STAGES; s++)
        issue_chunk(ab + s * STAGE_B, A0, W0, s * 16, row0, t);

#pragma unroll
    for (int cc = 0; cc < 8; cc++) {
        asm volatile("cp.async.wait_group 2;" ::: "memory");
        __syncthreads();
        const char* sm = smbase + (cc % 3) * STAGE_B;
        mma_chunk(sm, sm + 8192, c, wr, wc, g, tg);
        __syncthreads();
        if (cc + STAGES < 8) {
            int nc = cc + STAGES;
            int pass = nc >> 2;
            issue_chunk(ab + (nc % 3) * STAGE_B,
                        pass ? A1 : A0, pass ? W1 : W0, (nc & 3) * 16, row0, t);
        } else {
            asm volatile("cp.async.commit_group;" ::: "memory");
        }
    }

#pragma unroll
    for (int mt = 0; mt < 2; mt++) {
#pragma unroll
        for (int i = 0; i < 2; i++) {
            int r = row0 + wr * 32 + mt * 16 + g + i * 8;
            if (r >= NN) continue;
#pragma unroll
            for (int nt = 0; nt < 8; nt++) {
                int col = wc * 64 + nt * 8 + 2 * tg;
                float v0 = c[mt][nt][2 * i];
                float v1 = c[mt][nt][2 * i + 1];
                v0 = fmaxf(v0 * s_sc[col] + s_sh[col], 0.f);
                v1 = fmaxf(v1 * s_sc[col + 1] + s_sh[col + 1], 0.f);
                *(__half2*)(outh + (size_t)r * 128 + col) =
                    __float22half2_rn(make_float2(v0, v1));
            }
        }
    }
}

// ---------------- layer-2 dual GEMM + BN + ReLU fused with layer-3 GEMM ----------------
__global__ __launch_bounds__(256, 2) void k_gemm_dual_l2(
    const unsigned* __restrict__ A0, const unsigned* __restrict__ W0,
    const unsigned* __restrict__ A1, const unsigned* __restrict__ W1,
    const float* __restrict__ bias, const float* __restrict__ gamma,
    const float* __restrict__ beta, const float* __restrict__ rmean,
    const float* __restrict__ rvar,
    const unsigned* __restrict__ W3, const float* __restrict__ b3,
    __half* __restrict__ t3h, float* __restrict__ r3)
{
    extern __shared__ uint4 dyn4[];
    __shared__ float s_sc[128], s_sh[128];
    const int t = threadIdx.x;
    const int lane = t & 31, wid = t >> 5;
    const int wr = wid & 3, wc = wid >> 2;
    const int g = lane >> 2, tg = lane & 3;
    const int row0 = blockIdx.x * 128;

    uint32_t sb0 = su32(dyn4);
    uint32_t ab = (sb0 + 127u) & ~127u;
    char* smbase = (char*)dyn4 + (ab - sb0);

    if (t < 128) {
        float s = gamma[t] * rsqrtf(rvar[t] + 1e-5f);
        s_sc[t] = s;
        s_sh[t] = beta[t] + (bias[t] - rmean[t]) * s;
    }

    float c[2][8][4];
#pragma unroll
    for (int mt = 0; mt < 2; mt++)
#pragma unroll
        for (int nt = 0; nt < 8; nt++)
#pragma unroll
            for (int q = 0; q < 4; q++) c[mt][nt][q] = 0.f;

#pragma unroll
    for (int s = 0; s < STAGES; s++)
        issue_chunk(ab + s * STAGE_B, A0, W0, s * 16, row0, t);

#pragma unroll
    for (int cc = 0; cc < 8; cc++) {
        asm volatile("cp.async.wait_group 2;" ::: "memory");
        __syncthreads();
        const char* sm = smbase + (cc % 3) * STAGE_B;
        mma_chunk(sm, sm + 8192, c, wr, wc, g, tg);
        __syncthreads();
        if (cc + STAGES < 8) {
            int nc = cc + STAGES;
            int pass = nc >> 2;
            issue_chunk(ab + (nc % 3) * STAGE_B,
                        pass ? A1 : A0, pass ? W1 : W0, (nc & 3) * 16, row0, t);
        } else {
            asm volatile("cp.async.commit_group;" ::: "memory");
        }
    }
    asm volatile("cp.async.wait_group 0;" ::: "memory");
    __syncthreads();

    // stage W3c (32KB) into smem upper half via cp.async
#pragma unroll
    for (int kc = 0; kc < 4; kc++) {
#pragma unroll
        for (int j = 0; j < 2; j++) {
            int idx = t + j * 256;
            int row = idx >> 2, c16 = idx & 3;
            uint32_t dstp = ab + 32768 + kc * 8192 + SWZB(row * 64 + c16 * 16);
            const unsigned* bp = W3 + (size_t)row * 64 + kc * 16 + c16 * 4;
            asm volatile("cp.async.cg.shared.global [%0], [%1], 16, 16;"
                         :: "r"(dstp), "l"(bp) : "memory");
        }
    }
    asm volatile("cp.async.commit_group;" ::: "memory");

    // BN + ReLU -> fp16 h2 tile into smem lower half
#pragma unroll
    for (int mt = 0; mt < 2; mt++) {
#pragma unroll
        for (int i = 0; i < 2; i++) {
            int rl = wr * 32 + mt * 16 + g + i * 8;
#pragma unroll
            for (int nt = 0; nt < 8; nt++) {
                int col = wc * 64 + nt * 8 + 2 * tg;
                float v0 = fmaxf(c[mt][nt][2 * i] * s_sc[col] + s_sh[col], 0.f);
                float v1 = fmaxf(c[mt][nt][2 * i + 1] * s_sc[col + 1] + s_sh[col + 1], 0.f);
                __half2 h = __float22half2_rn(make_float2(v0, v1));
                int kc = col >> 5;
                int off = kc * 8192 + SWZB(rl * 64 + ((col & 31) >> 1) * 4);
                *(unsigned*)(smbase + off) = *(unsigned*)&h;
            }
        }
    }
    asm volatile("cp.async.wait_group 0;" ::: "memory");
    __syncthreads();

    // layer-3 GEMM: h2_tile @ W3c
#pragma unroll
    for (int mt = 0; mt < 2; mt++)
#pragma unroll
        for (int nt = 0; nt < 8; nt++)
#pragma unroll
            for (int q = 0; q < 4; q++) c[mt][nt][q] = 0.f;

#pragma unroll
    for (int kc = 0; kc < 4; kc++)
        mma_chunk(smbase + kc * 8192, smbase + 32768 + kc * 8192, c, wr, wc, g, tg);

#pragma unroll
    for (int mt = 0; mt < 2; mt++) {
#pragma unroll
        for (int i = 0; i < 2; i++) {
            int r = row0 + wr * 32 + mt * 16 + g + i * 8;
            if (r >= NN) continue;
#pragma unroll
            for (int nt = 0; nt < 8; nt++) {
                int col = wc * 64 + nt * 8 + 2 * tg;
                float v0 = c[mt][nt][2 * i];
                float v1 = c[mt][nt][2 * i + 1];
                if (col < 64) {
                    *(__half2*)(t3h + (size_t)r * 64 + col) =
                        __float22half2_rn(make_float2(v0, v1));
                } else {
                    int cc2 = col - 64;
                    v0 += b3[cc2]; v1 += b3[cc2 + 1];
                    *(float2*)(r3 + (size_t)r * 64 + cc2) = make_float2(v0, v1);
                }
            }
        }
    }
}

// ---------------- launch ----------------
extern "C" void kernel_launch(void* const* d_in, const int* in_sizes, int n_in,
                              void* d_out, int out_size) {
    const float* x   = (const float*)d_in[0];
    const int*   src = (const int*)d_in[1];
    const int*   dst = (const int*)d_in[2];
    const float* W1l = (const float*)d_in[3];
    const float* W1r = (const float*)d_in[4];
    const float* b1  = (const float*)d_in[5];
    const float* g1  = (const float*)d_in[6];
    const float* be1 = (const float*)d_in[7];
    const float* rm1 = (const float*)d_in[8];
    const float* rv1 = (const float*)d_in[9];
    const float* W2l = (const float*)d_in[10];
    const float* W2r = (const float*)d_in[11];
    const float* b2  = (const float*)d_in[12];
    const float* g2  = (const float*)d_in[13];
    const float* be2 = (const float*)d_in[14];
    const float* rm2 = (const float*)d_in[15];
    const float* rv2 = (const float*)d_in[16];
    const float* W3l = (const float*)d_in[17];
    const float* W3r = (const float*)d_in[18];
    const float* b3  = (const float*)d_in[19];
    float* out = (float*)d_out;
    int E = in_sizes[1];

    __half *p_xh, *p_aggh, *p_h1h, *p_t3h;
    float *p_r3;
    unsigned *p_w1l, *p_w1r, *p_w2l, *p_w2r, *p_w3c;
    cudaGetSymbolAddress((void**)&p_xh,   g_xh);
    cudaGetSymbolAddress((void**)&p_aggh, g_aggh);
    cudaGetSymbolAddress((void**)&p_h1h,  g_h1h);
    cudaGetSymbolAddress((void**)&p_t3h,  g_t3h);
    cudaGetSymbolAddress((void**)&p_r3,   g_r3);
    cudaGetSymbolAddress((void**)&p_w1l,  g_w1l);
    cudaGetSymbolAddress((void**)&p_w1r,  g_w1r);
    cudaGetSymbolAddress((void**)&p_w2l,  g_w2l);
    cudaGetSymbolAddress((void**)&p_w2r,  g_w2r);
    cudaGetSymbolAddress((void**)&p_w3c,  g_w3c);

    cudaFuncSetAttribute(k_gemm_dual,
                         cudaFuncAttributeMaxDynamicSharedMemorySize, DSMEM);
    cudaFuncSetAttribute(k_gemm_dual_l2,
                         cudaFuncAttributeMaxDynamicSharedMemorySize, DSMEM3);

    // merged histogram (+rank) + fp16 prep
    int total = (E >> 2) + NN * 32 + 5 * 8192;
    k_histprep<<<(total + 255) / 256, 256>>>(dst, E, x, W1l, W1r, W2l, W2r, W3l, W3r);
    k_scan1<<<NBLK_SCAN, 1024>>>();
    k_scan3<<<(NN + 1 + 255) / 256, 256>>>(E);
    k_scatter<<<((E >> 2) + 255) / 256, 256>>>(src, dst, E);

    const int gemm_blocks = NTILES;

    // layer 1
    k_aggr128h<<<NN / 8, 256>>>(p_xh, p_aggh);
    k_gemm_dual<<<gemm_blocks, 256, DSMEM>>>(
        (const unsigned*)p_aggh, p_w1l, (const unsigned*)p_xh, p_w1r,
        b1, g1, be1, rm1, rv1, p_h1h);
    // layer 2 + layer-3 GEMM fused
    k_aggr128h<<<NN / 8, 256>>>(p_h1h, p_aggh);
    k_gemm_dual_l2<<<gemm_blocks, 256, DSMEM3>>>(
        (const unsigned*)p_aggh, p_w2l, (const unsigned*)p_h1h, p_w2r,
        b2, g2, be2, rm2, rv2, p_w3c, b3, p_t3h, p_r3);
    // layer 3 aggregation + log_softmax fused
    k_agg_lsm<<<NN / 8, 256>>>(p_t3h, p_r3, out);
}